// round 12
// baseline (speedup 1.0000x reference)
#include <cuda_runtime.h>
#include <cuda_bf16.h>
#include <math.h>
#include <cstdint>

#define NROWS 65536
#define KDIM  512
#define A3    64
#define CWIN  16
#define DTOW  8
#define PLEN  96

// ---------------- scratch (device globals; no allocations allowed) ----------
__device__ float g_t   [(size_t)NROWS * A3];
__device__ float g_rep [(size_t)NROWS * A3];
__device__ float g_y   [(size_t)DTOW * NROWS * PLEN];   // [d][n][p] row-major
__device__ float g_G   [A3 * A3];        // Gram: rep^T rep
__device__ float g_m   [A3];             // colsum(rep)
__device__ float g_scale[DTOW * A3];
__device__ float g_shift[DTOW * A3];

// ---------------- mma.sync helper (HMMA, baseline PTX) -----------------------
__device__ __forceinline__ void mma16816(float* c, const uint32_t* a, const uint32_t* b) {
    asm volatile(
        "mma.sync.aligned.m16n8k16.row.col.f32.bf16.bf16.f32 "
        "{%0,%1,%2,%3}, {%4,%5,%6,%7}, {%8,%9}, {%0,%1,%2,%3};"
        : "+f"(c[0]), "+f"(c[1]), "+f"(c[2]), "+f"(c[3])
        : "r"(a[0]), "r"(a[1]), "r"(a[2]), "r"(a[3]), "r"(b[0]), "r"(b[1]));
}
__device__ __forceinline__ uint32_t pack_bf16x2(float lo, float hi_) {
    __nv_bfloat16 a = __float2bfloat16(lo), b = __float2bfloat16(hi_);
    return ((uint32_t)__bfloat16_as_ushort(b) << 16) | (uint32_t)__bfloat16_as_ushort(a);
}

// ---------------- K1 (mma): t = normalize(x @ shuzhihua)  [R10 form] ---------
// Block 0 additionally zeroes g_G / g_m (consumed by later kernels).
__global__ void __launch_bounds__(256) k1_gemm_norm_mma(const float* __restrict__ x,
                                                        const float* __restrict__ w) {
    __shared__ uint32_t cA[2][8][2][32][4];
    __shared__ uint32_t cB[2][8][2][32][2];
    __shared__ float rnorm[128];
    const int tid = threadIdx.x, wid = tid >> 5, lane = tid & 31;
    const int r0 = blockIdx.x * 128;
    const int mw = wid & 3, nw = wid >> 2;

    if (blockIdx.x == 0) {
        for (int i = tid; i < A3 * A3; i += 256) g_G[i] = 0.f;
        if (tid < A3) g_m[tid] = 0.f;
    }

    float accm[2][4][4];
#pragma unroll
    for (int mi = 0; mi < 2; mi++)
#pragma unroll
        for (int ni = 0; ni < 4; ni++)
#pragma unroll
            for (int j = 0; j < 4; j++) accm[mi][ni][j] = 0.f;

    const float* abase = x + (size_t)r0 * KDIM;

    for (int c = 0; c < 16; c++) {
        const int k0 = c * 32;
        __syncthreads();
#pragma unroll
        for (int it = 0; it < 8; it++) {
            int i = tid + it * 256;
            int r = i >> 4, kp = i & 15;
            int kg = k0 + kp * 2;
            float2 v = *(const float2*)&abase[(size_t)r * KDIM + kg];
            float h0 = __bfloat162float(__float2bfloat16(v.x));
            float h1 = __bfloat162float(__float2bfloat16(v.y));
            int ln = (r & 7) * 4 + (kp & 3);
            int rg = ((r >> 3) & 1) | ((kp & 4) >> 1);
            cA[0][r >> 4][kp >> 3][ln][rg] = pack_bf16x2(h0, h1);
            cA[1][r >> 4][kp >> 3][ln][rg] = pack_bf16x2(v.x - h0, v.y - h1);
        }
#pragma unroll
        for (int it = 0; it < 4; it++) {
            int i = tid + it * 256;
            int n = i & 63, kp = i >> 6;
            int kg = k0 + kp * 2;
            float w0 = w[(size_t)kg * A3 + n];
            float w1 = w[(size_t)(kg + 1) * A3 + n];
            float h0 = __bfloat162float(__float2bfloat16(w0));
            float h1 = __bfloat162float(__float2bfloat16(w1));
            int ln = (n & 7) * 4 + (kp & 3);
            int rg = (kp & 4) >> 2;
            cB[0][n >> 3][kp >> 3][ln][rg] = pack_bf16x2(h0, h1);
            cB[1][n >> 3][kp >> 3][ln][rg] = pack_bf16x2(w0 - h0, w1 - h1);
        }
        __syncthreads();
#pragma unroll
        for (int tk = 0; tk < 2; tk++) {
            uint32_t ah0[4], ah1[4], al0[4], al1[4];
            *(uint4*)ah0 = *(const uint4*)cA[0][mw * 2 + 0][tk][lane];
            *(uint4*)ah1 = *(const uint4*)cA[0][mw * 2 + 1][tk][lane];
            *(uint4*)al0 = *(const uint4*)cA[1][mw * 2 + 0][tk][lane];
            *(uint4*)al1 = *(const uint4*)cA[1][mw * 2 + 1][tk][lane];
#pragma unroll
            for (int ni = 0; ni < 4; ni++) {
                uint32_t bh[2], bl[2];
                *(uint2*)bh = *(const uint2*)cB[0][nw * 4 + ni][tk][lane];
                *(uint2*)bl = *(const uint2*)cB[1][nw * 4 + ni][tk][lane];
                mma16816(accm[0][ni], ah0, bh);
                mma16816(accm[1][ni], ah1, bh);
                mma16816(accm[0][ni], al0, bh);
                mma16816(accm[1][ni], al1, bh);
                mma16816(accm[0][ni], ah0, bl);
                mma16816(accm[1][ni], ah1, bl);
            }
        }
    }
    if (tid < 128) rnorm[tid] = 0.f;
    __syncthreads();
    float ssq[4] = {0.f, 0.f, 0.f, 0.f};
#pragma unroll
    for (int mi = 0; mi < 2; mi++)
#pragma unroll
        for (int ni = 0; ni < 4; ni++) {
            float* C = accm[mi][ni];
            ssq[2 * mi + 0] += C[0] * C[0] + C[1] * C[1];
            ssq[2 * mi + 1] += C[2] * C[2] + C[3] * C[3];
        }
#pragma unroll
    for (int off = 1; off < 4; off <<= 1)
#pragma unroll
        for (int j = 0; j < 4; j++)
            ssq[j] += __shfl_xor_sync(0xffffffffu, ssq[j], off);
    if ((lane & 3) == 0) {
        int rb = mw * 32 + (lane >> 2);
        atomicAdd(&rnorm[rb], ssq[0]);
        atomicAdd(&rnorm[rb + 8], ssq[1]);
        atomicAdd(&rnorm[rb + 16], ssq[2]);
        atomicAdd(&rnorm[rb + 24], ssq[3]);
    }
    __syncthreads();
    float* tb = g_t + (size_t)r0 * A3;
#pragma unroll
    for (int mi = 0; mi < 2; mi++) {
        int r = mw * 32 + mi * 16 + (lane >> 2);
        float s0 = 1.f / fmaxf(sqrtf(rnorm[r]), 1e-12f);
        float s1 = 1.f / fmaxf(sqrtf(rnorm[r + 8]), 1e-12f);
#pragma unroll
        for (int ni = 0; ni < 4; ni++) {
            int p = nw * 32 + ni * 8 + (lane & 3) * 2;
            float* C = accm[mi][ni];
            *(float2*)&tb[(size_t)r * A3 + p] = make_float2(C[0] * s0, C[1] * s0);
            *(float2*)&tb[(size_t)(r + 8) * A3 + p] = make_float2(C[2] * s1, C[3] * s1);
        }
    }
}

// ---------------- K2: windowed FIR; accumulates colsum m ---------------------
__global__ void __launch_bounds__(256) k2_window(const float* __restrict__ lw,
                                                 const float* __restrict__ lb,
                                                 float* __restrict__ rep_out) {
    __shared__ float ts[143 * 64];
    __shared__ float lws[16 * 64];
    __shared__ float sb[64];
    const int tid = threadIdx.x;
    const int r0 = blockIdx.x * 128;
    const int base = (r0 >= 15) ? (r0 - 15) : 0;
    const int nrows = r0 + 128 - base;

    for (int i = tid; i < nrows * 16; i += 256)
        ((float4*)ts)[i] = *(const float4*)&g_t[(size_t)base * A3 + (size_t)i * 4];
    for (int i = tid; i < 256; i += 256)
        ((float4*)lws)[i] = ((const float4*)lw)[i];
    if (tid < 64) {
        float s = 0.f;
#pragma unroll
        for (int j = 0; j < 16; j++) s += lb[j * 64 + tid];
        sb[tid] = s;
    }
    __syncthreads();

    const int c = tid & 63;
    const int rg = tid >> 6;
    float lwr[16];
#pragma unroll
    for (int j = 0; j < 16; j++) lwr[j] = lws[j * 64 + c];
    const float sbc = sb[c];

    float msum = 0.f;
    for (int rr = 0; rr < 32; rr++) {
        int i = r0 + rg * 32 + rr;
        float accv = sbc;
        if (i >= 15) {
            int off = i - 15 - base;
#pragma unroll
            for (int j = 0; j < 16; j++) accv += lwr[j] * ts[(off + j) * 64 + c];
        } else {
#pragma unroll
            for (int j = 0; j < 16; j++) {
                int s = (j < i) ? j : i;
                accv += lwr[j] * ts[s * 64 + c];
            }
        }
        g_rep[(size_t)i * A3 + c] = accv;
        msum += accv;
        if (rep_out) rep_out[(size_t)i * A3 + c] = accv;
    }
    atomicAdd(&g_m[c], msum);
}

// ---------------- KG: G = rep^T rep (fp32, atomic-accumulated) ---------------
__global__ void __launch_bounds__(256) kG_gram() {
    __shared__ float ts[64][64];
    const int tid = threadIdx.x;
    const int c1 = (tid >> 4) * 4, c2 = (tid & 15) * 4;
    const size_t r0 = (size_t)blockIdx.x * 512;

    float acc[4][4];
#pragma unroll
    for (int i = 0; i < 4; i++)
#pragma unroll
        for (int j = 0; j < 4; j++) acc[i][j] = 0.f;

    for (int t = 0; t < 8; t++) {
#pragma unroll
        for (int j = 0; j < 4; j++) {
            int idx = tid + j * 256;
            ((float4*)ts)[idx] = *(const float4*)&g_rep[(r0 + t * 64) * A3 + (size_t)idx * 4];
        }
        __syncthreads();
#pragma unroll 8
        for (int r = 0; r < 64; r++) {
            float4 a = *(const float4*)&ts[r][c1];
            float4 b = *(const float4*)&ts[r][c2];
            float av[4] = {a.x, a.y, a.z, a.w};
            float bv[4] = {b.x, b.y, b.z, b.w};
#pragma unroll
            for (int i = 0; i < 4; i++)
#pragma unroll
                for (int j = 0; j < 4; j++) acc[i][j] += av[i] * bv[j];
        }
        __syncthreads();
    }
#pragma unroll
    for (int i = 0; i < 4; i++)
#pragma unroll
        for (int j = 0; j < 4; j++)
            atomicAdd(&g_G[(c1 + i) * A3 + c2 + j], acc[i][j]);
}

// ---------------- K4': BN stats from (G, m) — one warp per (d,b) -------------
__global__ void __launch_bounds__(256) k4_stats2(const float* __restrict__ W1,
                                                 const float* __restrict__ b1,
                                                 const float* __restrict__ gamma,
                                                 const float* __restrict__ beta) {
    __shared__ float sG[A3 * A3];
    __shared__ float sw[8][A3];
    const int tid = threadIdx.x, wrp = tid >> 5, lane = tid & 31;
    const int gidx = blockIdx.x * 8 + wrp;   // 0..511
    const int d = gidx >> 6, b = gidx & 63;

#pragma unroll
    for (int j = 0; j < 4; j++) {
        int idx = tid + j * 256;
        ((float4*)sG)[idx] = *(const float4*)&g_G[(size_t)idx * 4];
    }
    __syncthreads();

    const float* W1d = W1 + (size_t)d * A3 * A3;
    float w0 = W1d[lane * A3 + b];
    float w1 = W1d[(lane + 32) * A3 + b];
    sw[wrp][lane] = w0;
    sw[wrp][lane + 32] = w1;
    __syncwarp();

    float t0 = 0.f, t1 = 0.f;
#pragma unroll 8
    for (int a2 = 0; a2 < A3; a2++) {
        float wv = sw[wrp][a2];
        t0 += sG[a2 * A3 + lane] * wv;        // G symmetric: G[a2][a] = G[a][a2]
        t1 += sG[a2 * A3 + lane + 32] * wv;
    }
    float qpart = w0 * t0 + w1 * t1;
    float lpart = g_m[lane] * w0 + g_m[lane + 32] * w1;
#pragma unroll
    for (int off = 1; off < 32; off <<= 1) {
        qpart += __shfl_xor_sync(0xffffffffu, qpart, off);
        lpart += __shfl_xor_sync(0xffffffffu, lpart, off);
    }
    if (lane == 0) {
        const float Nf = (float)NROWS, inv_n = 1.0f / Nf;
        float bb = b1[d * A3 + b];
        float mean = lpart * inv_n + bb;
        float sumsq = qpart + 2.f * bb * lpart + Nf * bb * bb;
        float var = sumsq * inv_n - mean * mean;
        float sc = rsqrtf(var + 1e-5f) * gamma[d * A3 + b];
        g_scale[d * A3 + b] = sc;
        g_shift[d * A3 + b] = beta[d * A3 + b] - mean * sc;
    }
}

// ---------------- K35 (fused): y = elu(bn(rep@W1+b1)) @ W2 + b2 --------------
// Phase 1: rep@W1 (MMA) -> BN+ELU in registers -> bf16 split -> canonical
// A-frags in smem. Phase 2: @W2 (MMA) -> y. g_h never materialized.
__global__ void __launch_bounds__(256) k35_towers(const float* __restrict__ W1,
                                                  const float* __restrict__ b1,
                                                  const float* __restrict__ W2,
                                                  const float* __restrict__ b2) {
    __shared__ __align__(16) unsigned char smb[45056 + 512];
    typedef uint32_t A1_t[8][2][32][4];
    typedef uint32_t B1_t[8][2][32][2];
    typedef uint32_t AF_t[8][4][32][4];
    typedef uint32_t B2_t[12][2][32][2];
    A1_t* cA1 = (A1_t*)smb;                       // [2] comp, 16KB
    B1_t* cB1 = (B1_t*)(smb + 16384);             // [2] comp,  8KB
    AF_t* cAF = (AF_t*)smb;                       // [2] comp, 32KB (phase 2)
    B2_t* cB2 = (B2_t*)(smb + 32768);             // [2] comp, 12KB
    float* sSc = (float*)(smb + 45056);
    float* sSh = sSc + 64;

    const int tid = threadIdx.x, wid = tid >> 5, lane = tid & 31;
    const int d = blockIdx.y;
    const int r0 = blockIdx.x * 128;
    const int mw = wid & 3, nw = wid >> 2;

    if (tid < 64) {
        float sc = g_scale[d * A3 + tid];
        sSc[tid] = sc;
        sSh[tid] = b1[d * A3 + tid] * sc + g_shift[d * A3 + tid];  // fold b1
    }

    // ================= phase 1: rep @ W1 =================
    float accm3[2][4][4];
#pragma unroll
    for (int mi = 0; mi < 2; mi++)
#pragma unroll
        for (int ni = 0; ni < 4; ni++)
#pragma unroll
            for (int j = 0; j < 4; j++) accm3[mi][ni][j] = 0.f;

    const float* abase = g_rep + (size_t)r0 * A3;
    const float* W1d = W1 + (size_t)d * A3 * A3;

    for (int c = 0; c < 2; c++) {
        const int k0 = c * 32;
        __syncthreads();
#pragma unroll
        for (int it = 0; it < 8; it++) {
            int i = tid + it * 256;
            int r = i >> 4, kp = i & 15;
            int kg = k0 + kp * 2;
            float2 v = *(const float2*)&abase[(size_t)r * A3 + kg];
            float h0 = __bfloat162float(__float2bfloat16(v.x));
            float h1 = __bfloat162float(__float2bfloat16(v.y));
            int ln = (r & 7) * 4 + (kp & 3);
            int rg = ((r >> 3) & 1) | ((kp & 4) >> 1);
            cA1[0][r >> 4][kp >> 3][ln][rg] = pack_bf16x2(h0, h1);
            cA1[1][r >> 4][kp >> 3][ln][rg] = pack_bf16x2(v.x - h0, v.y - h1);
        }
#pragma unroll
        for (int it = 0; it < 4; it++) {
            int i = tid + it * 256;
            int n = i & 63, kp = i >> 6;
            int kg = k0 + kp * 2;
            float w0 = W1d[(size_t)kg * A3 + n];
            float w1 = W1d[(size_t)(kg + 1) * A3 + n];
            float h0 = __bfloat162float(__float2bfloat16(w0));
            float h1 = __bfloat162float(__float2bfloat16(w1));
            int ln = (n & 7) * 4 + (kp & 3);
            int rg = (kp & 4) >> 2;
            cB1[0][n >> 3][kp >> 3][ln][rg] = pack_bf16x2(h0, h1);
            cB1[1][n >> 3][kp >> 3][ln][rg] = pack_bf16x2(w0 - h0, w1 - h1);
        }
        __syncthreads();
#pragma unroll
        for (int tk = 0; tk < 2; tk++) {
            uint32_t ah0[4], ah1[4], al0[4], al1[4];
            *(uint4*)ah0 = *(const uint4*)cA1[0][mw * 2 + 0][tk][lane];
            *(uint4*)ah1 = *(const uint4*)cA1[0][mw * 2 + 1][tk][lane];
            *(uint4*)al0 = *(const uint4*)cA1[1][mw * 2 + 0][tk][lane];
            *(uint4*)al1 = *(const uint4*)cA1[1][mw * 2 + 1][tk][lane];
#pragma unroll
            for (int ni = 0; ni < 4; ni++) {
                uint32_t bh[2], bl[2];
                *(uint2*)bh = *(const uint2*)cB1[0][nw * 4 + ni][tk][lane];
                *(uint2*)bl = *(const uint2*)cB1[1][nw * 4 + ni][tk][lane];
                mma16816(accm3[0][ni], ah0, bh);
                mma16816(accm3[1][ni], ah1, bh);
                mma16816(accm3[0][ni], al0, bh);
                mma16816(accm3[1][ni], al1, bh);
                mma16816(accm3[0][ni], ah0, bl);
                mma16816(accm3[1][ni], ah1, bl);
            }
        }
    }

    // ====== BN+ELU in registers; store phase-2 A-frags (canonical layout) ====
    __syncthreads();   // all phase-1 smem reads done; cAF overwrites cA1/cB1
    const int ln2 = (lane >> 2) * 4 + (lane & 3);
#pragma unroll
    for (int mi = 0; mi < 2; mi++)
#pragma unroll
        for (int ni = 0; ni < 4; ni++) {
            float* C = accm3[mi][ni];
            int p = nw * 32 + ni * 8 + (lane & 3) * 2;
            float sc0 = sSc[p], sc1 = sSc[p + 1];
            float sh0 = sSh[p], sh1 = sSh[p + 1];
            int tkr = nw * 2 + (ni >> 1);
            int rgb = (ni & 1) << 1;
            int tile = mw * 2 + mi;
            // row half 0 (row r): C[0], C[1] are k-adjacent pair
            float t0 = fmaf(C[0], sc0, sh0); t0 = t0 > 0.f ? t0 : expm1f(t0);
            float t1 = fmaf(C[1], sc1, sh1); t1 = t1 > 0.f ? t1 : expm1f(t1);
            float h0 = __bfloat162float(__float2bfloat16(t0));
            float h1 = __bfloat162float(__float2bfloat16(t1));
            cAF[0][tile][tkr][ln2][rgb | 0] = pack_bf16x2(h0, h1);
            cAF[1][tile][tkr][ln2][rgb | 0] = pack_bf16x2(t0 - h0, t1 - h1);
            // row half 1 (row r+8): C[2], C[3]
            float t2 = fmaf(C[2], sc0, sh0); t2 = t2 > 0.f ? t2 : expm1f(t2);
            float t3 = fmaf(C[3], sc1, sh1); t3 = t3 > 0.f ? t3 : expm1f(t3);
            float h2 = __bfloat162float(__float2bfloat16(t2));
            float h3 = __bfloat162float(__float2bfloat16(t3));
            cAF[0][tile][tkr][ln2][rgb | 1] = pack_bf16x2(h2, h3);
            cAF[1][tile][tkr][ln2][rgb | 1] = pack_bf16x2(t2 - h2, t3 - h3);
        }

    // ================= phase 2: h @ W2 =================
    float accm5[2][6][4];
#pragma unroll
    for (int mi = 0; mi < 2; mi++)
#pragma unroll
        for (int ni = 0; ni < 6; ni++)
#pragma unroll
            for (int j = 0; j < 4; j++) accm5[mi][ni][j] = 0.f;

    const float* W2d = W2 + (size_t)d * A3 * PLEN;
    for (int c2 = 0; c2 < 2; c2++) {
        const int k0 = c2 * 32;
        __syncthreads();
#pragma unroll
        for (int it = 0; it < 6; it++) {
            int i = tid + it * 256;
            int n = i % PLEN, kp = i / PLEN;
            int kg = k0 + kp * 2;
            float w0 = W2d[(size_t)kg * PLEN + n];
            float w1 = W2d[(size_t)(kg + 1) * PLEN + n];
            float h0 = __bfloat162float(__float2bfloat16(w0));
            float h1 = __bfloat162float(__float2bfloat16(w1));
            int ln = (n & 7) * 4 + (kp & 3);
            int rg = (kp & 4) >> 2;
            cB2[0][n >> 3][kp >> 3][ln][rg] = pack_bf16x2(h0, h1);
            cB2[1][n >> 3][kp >> 3][ln][rg] = pack_bf16x2(w0 - h0, w1 - h1);
        }
        __syncthreads();
#pragma unroll
        for (int tkl = 0; tkl < 2; tkl++) {
            int tk2 = c2 * 2 + tkl;
            uint32_t ah0[4], ah1[4], al0[4], al1[4];
            *(uint4*)ah0 = *(const uint4*)cAF[0][mw * 2 + 0][tk2][lane];
            *(uint4*)ah1 = *(const uint4*)cAF[0][mw * 2 + 1][tk2][lane];
            *(uint4*)al0 = *(const uint4*)cAF[1][mw * 2 + 0][tk2][lane];
            *(uint4*)al1 = *(const uint4*)cAF[1][mw * 2 + 1][tk2][lane];
#pragma unroll
            for (int ni = 0; ni < 6; ni++) {
                uint32_t bh[2], bl[2];
                *(uint2*)bh = *(const uint2*)cB2[0][nw * 6 + ni][tkl][lane];
                *(uint2*)bl = *(const uint2*)cB2[1][nw * 6 + ni][tkl][lane];
                mma16816(accm5[0][ni], ah0, bh);
                mma16816(accm5[1][ni], ah1, bh);
                mma16816(accm5[0][ni], al0, bh);
                mma16816(accm5[1][ni], al1, bh);
                mma16816(accm5[0][ni], ah0, bl);
                mma16816(accm5[1][ni], ah1, bl);
            }
        }
    }
    // epilogue: +b2, store y
    float* ybase = g_y + ((size_t)d * NROWS + r0) * PLEN;
#pragma unroll
    for (int mi = 0; mi < 2; mi++) {
        int r = mw * 32 + mi * 16 + (lane >> 2);
#pragma unroll
        for (int ni = 0; ni < 6; ni++) {
            int p = nw * 48 + ni * 8 + (lane & 3) * 2;
            float bb0 = b2[d * PLEN + p], bb1 = b2[d * PLEN + p + 1];
            float* C = accm5[mi][ni];
            *(float2*)&ybase[(size_t)r * PLEN + p] =
                make_float2(C[0] + bb0, C[1] + bb1);
            *(float2*)&ybase[(size_t)(r + 8) * PLEN + p] =
                make_float2(C[2] + bb0, C[3] + bb1);
        }
    }
}

// ---------------- K6: out[n, p*8+d] = g_y[d][n][p] ---------------------------
__global__ void __launch_bounds__(256) k6_interleave(float* __restrict__ out) {
    const size_t M = (size_t)NROWS * PLEN;
    size_t g = (size_t)blockIdx.x * 256 + threadIdx.x;
    float v[8];
#pragma unroll
    for (int d = 0; d < 8; d++) v[d] = g_y[(size_t)d * M + g];
    float4* o = (float4*)out;
    o[2 * g]     = make_float4(v[0], v[1], v[2], v[3]);
    o[2 * g + 1] = make_float4(v[4], v[5], v[6], v[7]);
}

// ---------------- launch ------------------------------------------------------
extern "C" void kernel_launch(void* const* d_in, const int* in_sizes, int n_in,
                              void* d_out, int out_size) {
    const float* x     = (const float*)d_in[0];
    const float* shu   = (const float*)d_in[1];
    const float* lw    = (const float*)d_in[2];
    const float* lb    = (const float*)d_in[3];
    const float* W1    = (const float*)d_in[4];
    const float* b1    = (const float*)d_in[5];
    const float* gamma = (const float*)d_in[6];
    const float* beta  = (const float*)d_in[7];
    const float* W2    = (const float*)d_in[8];
    const float* b2    = (const float*)d_in[9];
    float* out = (float*)d_out;

    float* rep_out = ((size_t)out_size >= (size_t)NROWS * (PLEN * DTOW + A3))
                         ? out + (size_t)NROWS * PLEN * DTOW
                         : nullptr;

    k1_gemm_norm_mma<<<NROWS / 128, 256>>>(x, shu);       // block 0 zeroes G, m
    k2_window<<<NROWS / 128, 256>>>(lw, lb, rep_out);     // accumulates m
    kG_gram<<<NROWS / 512, 256>>>();
    k4_stats2<<<64, 256>>>(W1, b1, gamma, beta);
    k35_towers<<<dim3(NROWS / 128, DTOW), 256>>>(W1, b1, W2, b2);
    k6_interleave<<<(NROWS * PLEN) / 256, 256>>>(out);
}

// round 14
// speedup vs baseline: 1.1789x; 1.1789x over previous
#include <cuda_runtime.h>
#include <cuda_bf16.h>
#include <math.h>
#include <cstdint>

#define NROWS 65536
#define KDIM  512
#define A3    64
#define CWIN  16
#define DTOW  8
#define PLEN  96

// ---------------- scratch (device globals; no allocations allowed) ----------
__device__ float g_t   [(size_t)NROWS * A3];
__device__ float g_rep [(size_t)NROWS * A3];
__device__ float g_y   [(size_t)DTOW * NROWS * PLEN];   // [d][n][p] row-major
__device__ float g_G   [A3 * A3];
__device__ float g_m   [A3];
__device__ float g_scale[DTOW * A3];
__device__ float g_shift[DTOW * A3];
// canonical split-fragment weight images (precomputed once per launch by kW)
__device__ uint32_t g_wB [16][2][8][2][32][2];          // shu   128KB
__device__ uint32_t g_wB1[DTOW][2][2][8][2][32][2];     // W1    128KB
__device__ uint32_t g_wB2[DTOW][2][2][12][2][32][2];    // W2    192KB

// ---------------- mma.sync helper (HMMA, baseline PTX) -----------------------
__device__ __forceinline__ void mma16816(float* c, const uint32_t* a, const uint32_t* b) {
    asm volatile(
        "mma.sync.aligned.m16n8k16.row.col.f32.bf16.bf16.f32 "
        "{%0,%1,%2,%3}, {%4,%5,%6,%7}, {%8,%9}, {%0,%1,%2,%3};"
        : "+f"(c[0]), "+f"(c[1]), "+f"(c[2]), "+f"(c[3])
        : "r"(a[0]), "r"(a[1]), "r"(a[2]), "r"(a[3]), "r"(b[0]), "r"(b[1]));
}
__device__ __forceinline__ uint32_t pack_bf16x2(float lo, float hi_) {
    __nv_bfloat16 a = __float2bfloat16(lo), b = __float2bfloat16(hi_);
    return ((uint32_t)__bfloat16_as_ushort(b) << 16) | (uint32_t)__bfloat16_as_ushort(a);
}

// ---------------- KW: precompute canonical split weights ---------------------
// blocks 0..15: shu chunk c; 16..31: W1 (d,chunk); 32..47: W2 (d,chunk)
__global__ void __launch_bounds__(256) kW_split(const float* __restrict__ w,
                                                const float* __restrict__ W1,
                                                const float* __restrict__ W2) {
    const int tid = threadIdx.x;
    const int blk = blockIdx.x;
    if (blk < 16) {
        const int c = blk;
#pragma unroll
        for (int j = 0; j < 4; j++) {
            int i = tid + j * 256;            // 0..1023
            int n = i & 63, kp = i >> 6;
            int kg = c * 32 + kp * 2;
            float w0 = w[(size_t)kg * A3 + n];
            float w1 = w[(size_t)(kg + 1) * A3 + n];
            float h0 = __bfloat162float(__float2bfloat16(w0));
            float h1 = __bfloat162float(__float2bfloat16(w1));
            int ln = (n & 7) * 4 + (kp & 3), rg = (kp & 4) >> 2;
            g_wB[c][0][n >> 3][kp >> 3][ln][rg] = pack_bf16x2(h0, h1);
            g_wB[c][1][n >> 3][kp >> 3][ln][rg] = pack_bf16x2(w0 - h0, w1 - h1);
        }
    } else if (blk < 32) {
        const int b = blk - 16, d = b >> 1, c = b & 1;
        const float* W1d = W1 + (size_t)d * A3 * A3;
#pragma unroll
        for (int j = 0; j < 4; j++) {
            int i = tid + j * 256;
            int n = i & 63, kp = i >> 6;
            int kg = c * 32 + kp * 2;
            float w0 = W1d[(size_t)kg * A3 + n];
            float w1 = W1d[(size_t)(kg + 1) * A3 + n];
            float h0 = __bfloat162float(__float2bfloat16(w0));
            float h1 = __bfloat162float(__float2bfloat16(w1));
            int ln = (n & 7) * 4 + (kp & 3), rg = (kp & 4) >> 2;
            g_wB1[d][c][0][n >> 3][kp >> 3][ln][rg] = pack_bf16x2(h0, h1);
            g_wB1[d][c][1][n >> 3][kp >> 3][ln][rg] = pack_bf16x2(w0 - h0, w1 - h1);
        }
    } else {
        const int b = blk - 32, d = b >> 1, c = b & 1;
        const float* W2d = W2 + (size_t)d * A3 * PLEN;
#pragma unroll
        for (int j = 0; j < 6; j++) {
            int i = tid + j * 256;            // 0..1535
            int n = i % PLEN, kp = i / PLEN;
            int kg = c * 32 + kp * 2;
            float w0 = W2d[(size_t)kg * PLEN + n];
            float w1 = W2d[(size_t)(kg + 1) * PLEN + n];
            float h0 = __bfloat162float(__float2bfloat16(w0));
            float h1 = __bfloat162float(__float2bfloat16(w1));
            int ln = (n & 7) * 4 + (kp & 3), rg = (kp & 4) >> 2;
            g_wB2[d][c][0][n >> 3][kp >> 3][ln][rg] = pack_bf16x2(h0, h1);
            g_wB2[d][c][1][n >> 3][kp >> 3][ln][rg] = pack_bf16x2(w0 - h0, w1 - h1);
        }
    }
}

// ---------------- K1 (mma): t = normalize(x @ shuzhihua) ---------------------
// Register-prefetched A fill; B via canonical copy. Block 0 zeroes G, m.
__global__ void __launch_bounds__(256) k1_gemm_norm_mma(const float* __restrict__ x) {
    __shared__ __align__(16) uint32_t cA[2][8][2][32][4];
    __shared__ __align__(16) uint32_t cB[2][8][2][32][2];
    __shared__ float rnorm[128];
    const int tid = threadIdx.x, wid = tid >> 5, lane = tid & 31;
    const int r0 = blockIdx.x * 128;
    const int mw = wid & 3, nw = wid >> 2;

    if (blockIdx.x == 0) {
        for (int i = tid; i < A3 * A3; i += 256) g_G[i] = 0.f;
        if (tid < A3) g_m[tid] = 0.f;
    }

    float accm[2][4][4];
#pragma unroll
    for (int mi = 0; mi < 2; mi++)
#pragma unroll
        for (int ni = 0; ni < 4; ni++)
#pragma unroll
            for (int j = 0; j < 4; j++) accm[mi][ni][j] = 0.f;

    const float* abase = x + (size_t)r0 * KDIM;

    // prefetch chunk 0
    float2 xa[8];
#pragma unroll
    for (int it = 0; it < 8; it++) {
        int i = tid + it * 256;
        int r = i >> 4, kp = i & 15;
        xa[it] = *(const float2*)&abase[(size_t)r * KDIM + kp * 2];
    }

    for (int c = 0; c < 16; c++) {
        // store prefetched A chunk (hi/lo split) + copy canonical B chunk
#pragma unroll
        for (int it = 0; it < 8; it++) {
            int i = tid + it * 256;
            int r = i >> 4, kp = i & 15;
            float2 v = xa[it];
            float h0 = __bfloat162float(__float2bfloat16(v.x));
            float h1 = __bfloat162float(__float2bfloat16(v.y));
            int ln = (r & 7) * 4 + (kp & 3);
            int rg = ((r >> 3) & 1) | ((kp & 4) >> 1);
            cA[0][r >> 4][kp >> 3][ln][rg] = pack_bf16x2(h0, h1);
            cA[1][r >> 4][kp >> 3][ln][rg] = pack_bf16x2(v.x - h0, v.y - h1);
        }
        {
            const uint4* src = (const uint4*)&g_wB[c][0][0][0][0][0];
            uint4* dst = (uint4*)cB;
            dst[tid] = src[tid];
            dst[tid + 256] = src[tid + 256];
        }
        __syncthreads();
        // prefetch next chunk while MMA runs
        if (c < 15) {
            int k0n = (c + 1) * 32;
#pragma unroll
            for (int it = 0; it < 8; it++) {
                int i = tid + it * 256;
                int r = i >> 4, kp = i & 15;
                xa[it] = *(const float2*)&abase[(size_t)r * KDIM + k0n + kp * 2];
            }
        }
#pragma unroll
        for (int tk = 0; tk < 2; tk++) {
            uint32_t ah0[4], ah1[4], al0[4], al1[4];
            *(uint4*)ah0 = *(const uint4*)cA[0][mw * 2 + 0][tk][lane];
            *(uint4*)ah1 = *(const uint4*)cA[0][mw * 2 + 1][tk][lane];
            *(uint4*)al0 = *(const uint4*)cA[1][mw * 2 + 0][tk][lane];
            *(uint4*)al1 = *(const uint4*)cA[1][mw * 2 + 1][tk][lane];
#pragma unroll
            for (int ni = 0; ni < 4; ni++) {
                uint32_t bh[2], bl[2];
                *(uint2*)bh = *(const uint2*)cB[0][nw * 4 + ni][tk][lane];
                *(uint2*)bl = *(const uint2*)cB[1][nw * 4 + ni][tk][lane];
                mma16816(accm[0][ni], ah0, bh);
                mma16816(accm[1][ni], ah1, bh);
                mma16816(accm[0][ni], al0, bh);
                mma16816(accm[1][ni], al1, bh);
                mma16816(accm[0][ni], ah0, bl);
                mma16816(accm[1][ni], ah1, bl);
            }
        }
        __syncthreads();
    }
    if (tid < 128) rnorm[tid] = 0.f;
    __syncthreads();
    float ssq[4] = {0.f, 0.f, 0.f, 0.f};
#pragma unroll
    for (int mi = 0; mi < 2; mi++)
#pragma unroll
        for (int ni = 0; ni < 4; ni++) {
            float* C = accm[mi][ni];
            ssq[2 * mi + 0] += C[0] * C[0] + C[1] * C[1];
            ssq[2 * mi + 1] += C[2] * C[2] + C[3] * C[3];
        }
#pragma unroll
    for (int off = 1; off < 4; off <<= 1)
#pragma unroll
        for (int j = 0; j < 4; j++)
            ssq[j] += __shfl_xor_sync(0xffffffffu, ssq[j], off);
    if ((lane & 3) == 0) {
        int rb = mw * 32 + (lane >> 2);
        atomicAdd(&rnorm[rb], ssq[0]);
        atomicAdd(&rnorm[rb + 8], ssq[1]);
        atomicAdd(&rnorm[rb + 16], ssq[2]);
        atomicAdd(&rnorm[rb + 24], ssq[3]);
    }
    __syncthreads();
    float* tb = g_t + (size_t)r0 * A3;
#pragma unroll
    for (int mi = 0; mi < 2; mi++) {
        int r = mw * 32 + mi * 16 + (lane >> 2);
        float s0 = 1.f / fmaxf(sqrtf(rnorm[r]), 1e-12f);
        float s1 = 1.f / fmaxf(sqrtf(rnorm[r + 8]), 1e-12f);
#pragma unroll
        for (int ni = 0; ni < 4; ni++) {
            int p = nw * 32 + ni * 8 + (lane & 3) * 2;
            float* C = accm[mi][ni];
            *(float2*)&tb[(size_t)r * A3 + p] = make_float2(C[0] * s0, C[1] * s0);
            *(float2*)&tb[(size_t)(r + 8) * A3 + p] = make_float2(C[2] * s1, C[3] * s1);
        }
    }
}

// ---------------- K2: windowed FIR; accumulates colsum m ---------------------
__global__ void __launch_bounds__(256) k2_window(const float* __restrict__ lw,
                                                 const float* __restrict__ lb,
                                                 float* __restrict__ rep_out) {
    __shared__ float ts[143 * 64];
    __shared__ float lws[16 * 64];
    __shared__ float sb[64];
    const int tid = threadIdx.x;
    const int r0 = blockIdx.x * 128;
    const int base = (r0 >= 15) ? (r0 - 15) : 0;
    const int nrows = r0 + 128 - base;

    for (int i = tid; i < nrows * 16; i += 256)
        ((float4*)ts)[i] = *(const float4*)&g_t[(size_t)base * A3 + (size_t)i * 4];
    for (int i = tid; i < 256; i += 256)
        ((float4*)lws)[i] = ((const float4*)lw)[i];
    if (tid < 64) {
        float s = 0.f;
#pragma unroll
        for (int j = 0; j < 16; j++) s += lb[j * 64 + tid];
        sb[tid] = s;
    }
    __syncthreads();

    const int c = tid & 63;
    const int rg = tid >> 6;
    float lwr[16];
#pragma unroll
    for (int j = 0; j < 16; j++) lwr[j] = lws[j * 64 + c];
    const float sbc = sb[c];

    float msum = 0.f;
    for (int rr = 0; rr < 32; rr++) {
        int i = r0 + rg * 32 + rr;
        float accv = sbc;
        if (i >= 15) {
            int off = i - 15 - base;
#pragma unroll
            for (int j = 0; j < 16; j++) accv += lwr[j] * ts[(off + j) * 64 + c];
        } else {
#pragma unroll
            for (int j = 0; j < 16; j++) {
                int s = (j < i) ? j : i;
                accv += lwr[j] * ts[s * 64 + c];
            }
        }
        g_rep[(size_t)i * A3 + c] = accv;
        msum += accv;
        if (rep_out) rep_out[(size_t)i * A3 + c] = accv;
    }
    atomicAdd(&g_m[c], msum);
}

// ---------------- KG: G = rep^T rep ------------------------------------------
__global__ void __launch_bounds__(256) kG_gram() {
    __shared__ float ts[64][64];
    const int tid = threadIdx.x;
    const int c1 = (tid >> 4) * 4, c2 = (tid & 15) * 4;
    const size_t r0 = (size_t)blockIdx.x * 512;

    float acc[4][4];
#pragma unroll
    for (int i = 0; i < 4; i++)
#pragma unroll
        for (int j = 0; j < 4; j++) acc[i][j] = 0.f;

    for (int t = 0; t < 8; t++) {
#pragma unroll
        for (int j = 0; j < 4; j++) {
            int idx = tid + j * 256;
            ((float4*)ts)[idx] = *(const float4*)&g_rep[(r0 + t * 64) * A3 + (size_t)idx * 4];
        }
        __syncthreads();
#pragma unroll 8
        for (int r = 0; r < 64; r++) {
            float4 a = *(const float4*)&ts[r][c1];
            float4 b = *(const float4*)&ts[r][c2];
            float av[4] = {a.x, a.y, a.z, a.w};
            float bv[4] = {b.x, b.y, b.z, b.w};
#pragma unroll
            for (int i = 0; i < 4; i++)
#pragma unroll
                for (int j = 0; j < 4; j++) acc[i][j] += av[i] * bv[j];
        }
        __syncthreads();
    }
#pragma unroll
    for (int i = 0; i < 4; i++)
#pragma unroll
        for (int j = 0; j < 4; j++)
            atomicAdd(&g_G[(c1 + i) * A3 + c2 + j], acc[i][j]);
}

// ---------------- K4': BN stats from (G, m) ----------------------------------
__global__ void __launch_bounds__(256) k4_stats2(const float* __restrict__ W1,
                                                 const float* __restrict__ b1,
                                                 const float* __restrict__ gamma,
                                                 const float* __restrict__ beta) {
    __shared__ float sG[A3 * A3];
    __shared__ float sw[8][A3];
    const int tid = threadIdx.x, wrp = tid >> 5, lane = tid & 31;
    const int gidx = blockIdx.x * 8 + wrp;
    const int d = gidx >> 6, b = gidx & 63;

#pragma unroll
    for (int j = 0; j < 4; j++) {
        int idx = tid + j * 256;
        ((float4*)sG)[idx] = *(const float4*)&g_G[(size_t)idx * 4];
    }
    __syncthreads();

    const float* W1d = W1 + (size_t)d * A3 * A3;
    float w0 = W1d[lane * A3 + b];
    float w1 = W1d[(lane + 32) * A3 + b];
    sw[wrp][lane] = w0;
    sw[wrp][lane + 32] = w1;
    __syncwarp();

    float t0 = 0.f, t1 = 0.f;
#pragma unroll 8
    for (int a2 = 0; a2 < A3; a2++) {
        float wv = sw[wrp][a2];
        t0 += sG[a2 * A3 + lane] * wv;
        t1 += sG[a2 * A3 + lane + 32] * wv;
    }
    float qpart = w0 * t0 + w1 * t1;
    float lpart = g_m[lane] * w0 + g_m[lane + 32] * w1;
#pragma unroll
    for (int off = 1; off < 32; off <<= 1) {
        qpart += __shfl_xor_sync(0xffffffffu, qpart, off);
        lpart += __shfl_xor_sync(0xffffffffu, lpart, off);
    }
    if (lane == 0) {
        const float Nf = (float)NROWS, inv_n = 1.0f / Nf;
        float bb = b1[d * A3 + b];
        float mean = lpart * inv_n + bb;
        float sumsq = qpart + 2.f * bb * lpart + Nf * bb * bb;
        float var = sumsq * inv_n - mean * mean;
        float sc = rsqrtf(var + 1e-5f) * gamma[d * A3 + b];
        g_scale[d * A3 + b] = sc;
        g_shift[d * A3 + b] = beta[d * A3 + b] - mean * sc;
    }
}

// ---------------- K35 (fused): y = elu(bn(rep@W1+b1)) @ W2 + b2 --------------
__global__ void __launch_bounds__(256) k35_towers(const float* __restrict__ b1,
                                                  const float* __restrict__ b2) {
    __shared__ __align__(16) unsigned char smb[45056 + 512];
    typedef uint32_t A1_t[8][2][32][4];
    typedef uint32_t AF_t[8][4][32][4];
    typedef uint32_t B2_t[12][2][32][2];
    A1_t* cA1 = (A1_t*)smb;
    uint32_t* cB1raw = (uint32_t*)(smb + 16384);   // [2][8][2][32][2] = 2048 words
    AF_t* cAF = (AF_t*)smb;
    B2_t* cB2 = (B2_t*)(smb + 32768);
    uint32_t* cB2raw = (uint32_t*)(smb + 32768);   // [2][12][2][32][2] = 3072 words
    float* sSc = (float*)(smb + 45056);
    float* sSh = sSc + 64;

    const int tid = threadIdx.x, wid = tid >> 5, lane = tid & 31;
    const int d = blockIdx.y;
    const int r0 = blockIdx.x * 128;
    const int mw = wid & 3, nw = wid >> 2;

    if (tid < 64) {
        float sc = g_scale[d * A3 + tid];
        sSc[tid] = sc;
        sSh[tid] = b1[d * A3 + tid] * sc + g_shift[d * A3 + tid];
    }

    // ================= phase 1: rep @ W1 =================
    float accm3[2][4][4];
#pragma unroll
    for (int mi = 0; mi < 2; mi++)
#pragma unroll
        for (int ni = 0; ni < 4; ni++)
#pragma unroll
            for (int j = 0; j < 4; j++) accm3[mi][ni][j] = 0.f;

    const float* abase = g_rep + (size_t)r0 * A3;

    for (int c = 0; c < 2; c++) {
        const int k0 = c * 32;
        __syncthreads();
#pragma unroll
        for (int it = 0; it < 8; it++) {
            int i = tid + it * 256;
            int r = i >> 4, kp = i & 15;
            int kg = k0 + kp * 2;
            float2 v = *(const float2*)&abase[(size_t)r * A3 + kg];
            float h0 = __bfloat162float(__float2bfloat16(v.x));
            float h1 = __bfloat162float(__float2bfloat16(v.y));
            int ln = (r & 7) * 4 + (kp & 3);
            int rg = ((r >> 3) & 1) | ((kp & 4) >> 1);
            cA1[0][r >> 4][kp >> 3][ln][rg] = pack_bf16x2(h0, h1);
            cA1[1][r >> 4][kp >> 3][ln][rg] = pack_bf16x2(v.x - h0, v.y - h1);
        }
        {
            const uint4* src = (const uint4*)&g_wB1[d][c][0][0][0][0][0];
            uint4* dst = (uint4*)cB1raw;
            dst[tid] = src[tid];
            dst[tid + 256] = src[tid + 256];
        }
        __syncthreads();
        const uint32_t (*cB1)[8][2][32][2] = (const uint32_t (*)[8][2][32][2])cB1raw;
#pragma unroll
        for (int tk = 0; tk < 2; tk++) {
            uint32_t ah0[4], ah1[4], al0[4], al1[4];
            *(uint4*)ah0 = *(const uint4*)cA1[0][mw * 2 + 0][tk][lane];
            *(uint4*)ah1 = *(const uint4*)cA1[0][mw * 2 + 1][tk][lane];
            *(uint4*)al0 = *(const uint4*)cA1[1][mw * 2 + 0][tk][lane];
            *(uint4*)al1 = *(const uint4*)cA1[1][mw * 2 + 1][tk][lane];
#pragma unroll
            for (int ni = 0; ni < 4; ni++) {
                uint32_t bh[2], bl[2];
                *(uint2*)bh = *(const uint2*)cB1[0][nw * 4 + ni][tk][lane];
                *(uint2*)bl = *(const uint2*)cB1[1][nw * 4 + ni][tk][lane];
                mma16816(accm3[0][ni], ah0, bh);
                mma16816(accm3[1][ni], ah1, bh);
                mma16816(accm3[0][ni], al0, bh);
                mma16816(accm3[1][ni], al1, bh);
                mma16816(accm3[0][ni], ah0, bl);
                mma16816(accm3[1][ni], ah1, bl);
            }
        }
    }

    // ====== BN+ELU in registers; store phase-2 A-frags ======
    __syncthreads();
    const int ln2 = (lane >> 2) * 4 + (lane & 3);
#pragma unroll
    for (int mi = 0; mi < 2; mi++)
#pragma unroll
        for (int ni = 0; ni < 4; ni++) {
            float* C = accm3[mi][ni];
            int p = nw * 32 + ni * 8 + (lane & 3) * 2;
            float sc0 = sSc[p], sc1 = sSc[p + 1];
            float sh0 = sSh[p], sh1 = sSh[p + 1];
            int tkr = nw * 2 + (ni >> 1);
            int rgb = (ni & 1) << 1;
            int tile = mw * 2 + mi;
            float t0 = fmaf(C[0], sc0, sh0); t0 = t0 > 0.f ? t0 : expm1f(t0);
            float t1 = fmaf(C[1], sc1, sh1); t1 = t1 > 0.f ? t1 : expm1f(t1);
            float h0 = __bfloat162float(__float2bfloat16(t0));
            float h1 = __bfloat162float(__float2bfloat16(t1));
            cAF[0][tile][tkr][ln2][rgb | 0] = pack_bf16x2(h0, h1);
            cAF[1][tile][tkr][ln2][rgb | 0] = pack_bf16x2(t0 - h0, t1 - h1);
            float t2 = fmaf(C[2], sc0, sh0); t2 = t2 > 0.f ? t2 : expm1f(t2);
            float t3 = fmaf(C[3], sc1, sh1); t3 = t3 > 0.f ? t3 : expm1f(t3);
            float h2 = __bfloat162float(__float2bfloat16(t2));
            float h3 = __bfloat162float(__float2bfloat16(t3));
            cAF[0][tile][tkr][ln2][rgb | 1] = pack_bf16x2(h2, h3);
            cAF[1][tile][tkr][ln2][rgb | 1] = pack_bf16x2(t2 - h2, t3 - h3);
        }

    // ================= phase 2: h @ W2 =================
    float accm5[2][6][4];
#pragma unroll
    for (int mi = 0; mi < 2; mi++)
#pragma unroll
        for (int ni = 0; ni < 6; ni++)
#pragma unroll
            for (int j = 0; j < 4; j++) accm5[mi][ni][j] = 0.f;

    for (int c2 = 0; c2 < 2; c2++) {
        __syncthreads();
        {
            const uint4* src = (const uint4*)&g_wB2[d][c2][0][0][0][0][0];
            uint4* dst = (uint4*)cB2raw;
            dst[tid] = src[tid];
            dst[tid + 256] = src[tid + 256];
            dst[tid + 512] = src[tid + 512];
        }
        __syncthreads();
#pragma unroll
        for (int tkl = 0; tkl < 2; tkl++) {
            int tk2 = c2 * 2 + tkl;
            uint32_t ah0[4], ah1[4], al0[4], al1[4];
            *(uint4*)ah0 = *(const uint4*)cAF[0][mw * 2 + 0][tk2][lane];
            *(uint4*)ah1 = *(const uint4*)cAF[0][mw * 2 + 1][tk2][lane];
            *(uint4*)al0 = *(const uint4*)cAF[1][mw * 2 + 0][tk2][lane];
            *(uint4*)al1 = *(const uint4*)cAF[1][mw * 2 + 1][tk2][lane];
#pragma unroll
            for (int ni = 0; ni < 6; ni++) {
                uint32_t bh[2], bl[2];
                *(uint2*)bh = *(const uint2*)cB2[0][nw * 6 + ni][tkl][lane];
                *(uint2*)bl = *(const uint2*)cB2[1][nw * 6 + ni][tkl][lane];
                mma16816(accm5[0][ni], ah0, bh);
                mma16816(accm5[1][ni], ah1, bh);
                mma16816(accm5[0][ni], al0, bh);
                mma16816(accm5[1][ni], al1, bh);
                mma16816(accm5[0][ni], ah0, bl);
                mma16816(accm5[1][ni], ah1, bl);
            }
        }
    }
    float* ybase = g_y + ((size_t)d * NROWS + r0) * PLEN;
#pragma unroll
    for (int mi = 0; mi < 2; mi++) {
        int r = mw * 32 + mi * 16 + (lane >> 2);
#pragma unroll
        for (int ni = 0; ni < 6; ni++) {
            int p = nw * 48 + ni * 8 + (lane & 3) * 2;
            float bb0 = b2[d * PLEN + p], bb1 = b2[d * PLEN + p + 1];
            float* C = accm5[mi][ni];
            *(float2*)&ybase[(size_t)r * PLEN + p] =
                make_float2(C[0] + bb0, C[1] + bb1);
            *(float2*)&ybase[(size_t)(r + 8) * PLEN + p] =
                make_float2(C[2] + bb0, C[3] + bb1);
        }
    }
}

// ---------------- K6: out[n, p*8+d] = g_y[d][n][p] ---------------------------
__global__ void __launch_bounds__(256) k6_interleave(float* __restrict__ out) {
    const size_t M = (size_t)NROWS * PLEN;
    size_t g = (size_t)blockIdx.x * 256 + threadIdx.x;
    float v[8];
#pragma unroll
    for (int d = 0; d < 8; d++) v[d] = g_y[(size_t)d * M + g];
    float4* o = (float4*)out;
    o[2 * g]     = make_float4(v[0], v[1], v[2], v[3]);
    o[2 * g + 1] = make_float4(v[4], v[5], v[6], v[7]);
}

// ---------------- launch ------------------------------------------------------
extern "C" void kernel_launch(void* const* d_in, const int* in_sizes, int n_in,
                              void* d_out, int out_size) {
    const float* x     = (const float*)d_in[0];
    const float* shu   = (const float*)d_in[1];
    const float* lw    = (const float*)d_in[2];
    const float* lb    = (const float*)d_in[3];
    const float* W1    = (const float*)d_in[4];
    const float* b1    = (const float*)d_in[5];
    const float* gamma = (const float*)d_in[6];
    const float* beta  = (const float*)d_in[7];
    const float* W2    = (const float*)d_in[8];
    const float* b2    = (const float*)d_in[9];
    float* out = (float*)d_out;

    float* rep_out = ((size_t)out_size >= (size_t)NROWS * (PLEN * DTOW + A3))
                         ? out + (size_t)NROWS * PLEN * DTOW
                         : nullptr;

    kW_split<<<48, 256>>>(shu, W1, W2);
    k1_gemm_norm_mma<<<NROWS / 128, 256>>>(x);            // block 0 zeroes G, m
    k2_window<<<NROWS / 128, 256>>>(lw, lb, rep_out);     // accumulates m
    kG_gram<<<NROWS / 512, 256>>>();
    k4_stats2<<<64, 256>>>(W1, b1, gamma, beta);
    k35_towers<<<dim3(NROWS / 128, DTOW), 256>>>(b1, b2);
    k6_interleave<<<(NROWS * PLEN) / 256, 256>>>(out);
}